// round 5
// baseline (speedup 1.0000x reference)
#include <cuda_runtime.h>
#include <math.h>
#include <stdint.h>

#define NN 50000
#define NE 800000
#define NF 256
#define NH 64
#define NC 16

// ---------------- static scratch (no allocations allowed) ----------------
__device__ __align__(256) float g_Z [NN * 192];   // GEMM input staging
__device__ __align__(256) float g_h [NN * NH];
__device__ __align__(256) float g_y [NN * NH];
__device__ __align__(256) float g_t [NN * NH];
__device__ __align__(256) float g_k [NN * NH];
__device__ __align__(256) float g_ka[NN * NH];
__device__ __align__(256) float g_hf[NN * NH];
__device__ __align__(256) float g_G2[NN * 48];
__device__ __align__(256) float g_B1[NF * 192];   // [W1_0 | W1_1-W1_0 | R1]
__device__ __align__(256) float g_BA[192 * NH];   // [Wa_0; Wa_1-Wa_0; Ra]
__device__ __align__(256) float g_BB[192 * NH];
__device__ __align__(256) float g_B2[NH * 48];
// pre-split (tf32 hi/lo) + fragment-permuted B for tensor-core GEMM
__device__ __align__(256) float g_B1p[NF * 192 * 2];
__device__ __align__(256) float g_BAp[192 * NH * 2];
__device__ __align__(256) float g_BBp[192 * NH * 2];
__device__ __align__(256) float g_B2p[NH * 64 * 2];   // padded N 48->64
__device__ int   g_rp[NN + 1];
__device__ int   g_wp[NN];
__device__ int   g_cnt[NN];
__device__ float g_invd[NN];
__device__ int   g_esrc[NE];
__device__ __align__(256) float g_ep[NE];

// ---------------- tf32 helpers ----------------
__device__ __forceinline__ float tf32r(float x) {
    uint32_t u;
    asm("cvt.rna.tf32.f32 %0, %1;" : "=r"(u) : "f"(x));
    return __uint_as_float(u);
}

#define MMA_TF32(d, a0, a1, a2, a3, b0, b1)                                   \
    asm volatile(                                                             \
        "mma.sync.aligned.m16n8k8.row.col.f32.tf32.tf32.f32 "                 \
        "{%0,%1,%2,%3},{%4,%5,%6,%7},{%8,%9},{%0,%1,%2,%3};"                  \
        : "+f"((d)[0]), "+f"((d)[1]), "+f"((d)[2]), "+f"((d)[3])              \
        : "r"(__float_as_uint(a0)), "r"(__float_as_uint(a1)),                 \
          "r"(__float_as_uint(a2)), "r"(__float_as_uint(a3)),                 \
          "r"(__float_as_uint(b0)), "r"(__float_as_uint(b1)))

// ---------------- CSR build ----------------
__global__ void k_zero() {
    int i = blockIdx.x * blockDim.x + threadIdx.x;
    if (i < NN) g_cnt[i] = 0;
}

__global__ void k_hist(const int* __restrict__ dst) {
    int e = blockIdx.x * blockDim.x + threadIdx.x;
    if (e < NE) atomicAdd(&g_cnt[dst[e]], 1);
}

__global__ void k_scan() {
    __shared__ int wsum[32];
    __shared__ int carry_s;
    int tid = threadIdx.x, lane = tid & 31, wid = tid >> 5;
    if (tid == 0) carry_s = 0;
    __syncthreads();
    for (int base = 0; base < NN; base += 1024) {
        int i = base + tid;
        int v = (i < NN) ? g_cnt[i] : 0;
        int x = v;
        #pragma unroll
        for (int off = 1; off < 32; off <<= 1) {
            int t = __shfl_up_sync(0xffffffffu, x, off);
            if (lane >= off) x += t;
        }
        if (lane == 31) wsum[wid] = x;
        __syncthreads();
        if (wid == 0) {
            int s = wsum[lane];
            #pragma unroll
            for (int off = 1; off < 32; off <<= 1) {
                int t = __shfl_up_sync(0xffffffffu, s, off);
                if (lane >= off) s += t;
            }
            wsum[lane] = s;
        }
        __syncthreads();
        int excl = carry_s + (wid > 0 ? wsum[wid - 1] : 0) + x - v;
        if (i < NN) {
            g_rp[i]  = excl;
            g_wp[i]  = excl;
            g_invd[i] = 1.0f / (float)(v > 0 ? v : 1);
        }
        __syncthreads();
        if (tid == 0) carry_s += wsum[31];
        __syncthreads();
    }
    if (threadIdx.x == 0) g_rp[NN] = carry_s;
}

__global__ void k_scatter(const int* __restrict__ src, const int* __restrict__ dst,
                          const float* __restrict__ p) {
    int e = blockIdx.x * blockDim.x + threadIdx.x;
    if (e < NE) {
        int d   = dst[e];
        int pos = atomicAdd(&g_wp[d], 1);
        g_esrc[pos] = src[e];
        g_ep[pos]   = p[e];
    }
}

// ---------------- weight prep ----------------
__global__ void k_prep_tf(const float* __restrict__ W, const float* __restrict__ R,
                          float* __restrict__ B, int Cin, int Cout) {
    int i = blockIdx.x * blockDim.x + threadIdx.x;
    int tot = Cin * 3 * Cout;
    if (i >= tot) return;
    int r = i / (3 * Cout), c = i % (3 * Cout);
    float v;
    if (c < Cout)            v = W[r * Cout + c];
    else if (c < 2 * Cout)   v = W[Cin * Cout + r * Cout + (c - Cout)] - W[r * Cout + (c - Cout)];
    else                     v = R[r * Cout + (c - 2 * Cout)];
    B[i] = v;
}

__global__ void k_prep_af(const float* __restrict__ W, const float* __restrict__ R,
                          float* __restrict__ B, int C) {
    int i = blockIdx.x * blockDim.x + threadIdx.x;
    int tot = 3 * C * C;
    if (i >= tot) return;
    int r = i / C, c = i % C;
    float v;
    if (r < C)          v = W[r * C + c];
    else if (r < 2 * C) v = W[C * C + (r - C) * C + c] - W[(r - C) * C + c];
    else                v = R[(r - 2 * C) * C + c];
    B[i] = v;
}

// split into tf32 hi/lo and permute into m16n8k8 B-fragment order.
// layout: [k/8][n/8][lane(= (n%8)*4 + k%4)][4] = {b0hi, b1hi, b0lo, b1lo}
__global__ void k_permB(const float* __restrict__ B, float* __restrict__ Bp,
                        int K, int N, int Npad) {
    int i = blockIdx.x * blockDim.x + threadIdx.x;
    if (i >= K * Npad) return;
    int k = i / Npad, n = i % Npad;
    float v = (n < N) ? B[k * N + n] : 0.0f;
    float hi = tf32r(v);
    float lo = tf32r(v - hi);
    int lane = (n & 7) * 4 + (k & 3);
    int pos = ((((k >> 3) * (Npad >> 3) + (n >> 3)) * 32) + lane) * 4;
    int off = (k >> 2) & 1;
    Bp[pos + off]     = hi;
    Bp[pos + 2 + off] = lo;
}

// ---------------- 3xTF32 tensor-core GEMM ----------------
// C[M,Nw] = A[M,K] @ B[K,N] (+bias) (+RK4 epilogue). K % 32 == 0.
// N = padded fragment-grid width (% 64 == 0, matches k_permB Npad);
// Nw = actual output width (epilogue guard); ldc = output row stride.
// block: 256 thr = 8 warps (4 x 2 over M x N), warp tile 32x32.
__global__ void __launch_bounds__(256) k_gemm_tc(
    const float* __restrict__ A, const float* __restrict__ Bp,
    float* __restrict__ C, const float* __restrict__ bias,
    int M, int K, int N, int Nw, int ldc,
    int mode, const float* __restrict__ hin, float* __restrict__ ynext,
    float* __restrict__ kacc, float ccoef, float wcoef, int kinit)
{
    // A staged in fragment order: [ik 0..3][wm 0..3][im 0..1][lane][hi4 | lo4]
    __shared__ __align__(16) float As[4 * 4 * 2 * 32 * 8];   // 32 KB
    int tid = threadIdx.x, lane = tid & 31, wid = tid >> 5;
    int bm = blockIdx.x * 128, bn = blockIdx.y * 64;
    int wm = wid >> 1;          // 0..3  (rows wm*32)
    int wn = wid & 1;           // 0..1  (cols wn*32)
    int N8 = N >> 3;
    int n8base = (bn >> 3) + wn * 4;

    float acc[2][4][4];
    #pragma unroll
    for (int im = 0; im < 2; im++)
        #pragma unroll
        for (int jn = 0; jn < 4; jn++)
            #pragma unroll
            for (int q = 0; q < 4; q++) acc[im][jn][q] = 0.0f;

    for (int k0 = 0; k0 < K; k0 += 32) {
        // ---- fill As (128x32 tile), split hi/lo, permuted ----
        #pragma unroll
        for (int q = 0; q < 4; q++) {
            int s  = q * 256 + tid;
            int m  = s >> 3;
            int kq = (s & 7) << 2;
            float4 v = make_float4(0.f, 0.f, 0.f, 0.f);
            int gr = bm + m;
            if (gr < M) v = *(const float4*)(A + (size_t)gr * K + k0 + kq);
            int ik = kq >> 3, khalf = (kq >> 2) & 1;
            int ln = (m & 7) * 4;
            int wmi = m >> 5, imi = (m >> 4) & 1;
            int rb = ((m >> 3) & 1) + 2 * khalf;
            float* base = As + ((((ik * 4 + wmi) * 2 + imi) * 32 + ln) * 8);
            float vv[4] = {v.x, v.y, v.z, v.w};
            #pragma unroll
            for (int j = 0; j < 4; j++) {
                float x  = vv[j];
                float hi = tf32r(x);
                float lo = tf32r(x - hi);
                base[j * 8 + rb]     = hi;
                base[j * 8 + 4 + rb] = lo;
            }
        }
        __syncthreads();

        #pragma unroll
        for (int ik = 0; ik < 4; ik++) {
            int ikg = (k0 >> 3) + ik;
            float4 ahi[2], alo[2];
            #pragma unroll
            for (int im = 0; im < 2; im++) {
                const float4* p = (const float4*)(As + ((((ik * 4 + wm) * 2 + im) * 32 + lane) * 8));
                ahi[im] = p[0];
                alo[im] = p[1];
            }
            float4 bf[4];
            #pragma unroll
            for (int jn = 0; jn < 4; jn++)
                bf[jn] = *(const float4*)(Bp + (size_t)(((ikg * N8 + n8base + jn) * 32 + lane) * 4));

            #pragma unroll
            for (int im = 0; im < 2; im++)
                #pragma unroll
                for (int jn = 0; jn < 4; jn++) {
                    MMA_TF32(acc[im][jn], alo[im].x, alo[im].y, alo[im].z, alo[im].w,
                             bf[jn].x, bf[jn].y);                    // loA * hiB
                    MMA_TF32(acc[im][jn], ahi[im].x, ahi[im].y, ahi[im].z, ahi[im].w,
                             bf[jn].z, bf[jn].w);                    // hiA * loB
                    MMA_TF32(acc[im][jn], ahi[im].x, ahi[im].y, ahi[im].z, ahi[im].w,
                             bf[jn].x, bf[jn].y);                    // hiA * hiB
                }
        }
        __syncthreads();
    }

    // ---- epilogue ----
    int r0 = bm + wm * 32 + (lane >> 2);
    int cb = bn + wn * 32 + (lane & 3) * 2;
    #pragma unroll
    for (int im = 0; im < 2; im++) {
        #pragma unroll
        for (int half = 0; half < 2; half++) {
            int r = r0 + im * 16 + half * 8;
            if (r >= M) continue;
            #pragma unroll
            for (int jn = 0; jn < 4; jn++) {
                int c = cb + jn * 8;
                if (c >= Nw) continue;
                float v0 = acc[im][jn][half * 2 + 0];
                float v1 = acc[im][jn][half * 2 + 1];
                if (bias) { v0 += bias[c]; v1 += bias[c + 1]; }
                *(float2*)(C + (size_t)r * ldc + c) = make_float2(v0, v1);
                if (mode) {            // Nw == 64 path
                    size_t ei = (size_t)r * 64 + c;
                    if (ynext) {
                        ynext[ei]     = hin[ei]     + ccoef * v0;
                        ynext[ei + 1] = hin[ei + 1] + ccoef * v1;
                    }
                    if (kinit) {
                        kacc[ei]     = wcoef * v0;
                        kacc[ei + 1] = wcoef * v1;
                    } else {
                        kacc[ei]     += wcoef * v0;
                        kacc[ei + 1] += wcoef * v1;
                    }
                }
            }
        }
    }
}

// ---------------- edge kernels (CSR, warp per node) ----------------
__global__ void k_agg(const float* __restrict__ yin) {
    int warp = (blockIdx.x * blockDim.x + threadIdx.x) >> 5;
    if (warp >= NN) return;
    int v = warp, lane = threadIdx.x & 31, c = lane * 2;
    float a0x = 0.f, a0y = 0.f, a1x = 0.f, a1y = 0.f;
    int s = g_rp[v], e = g_rp[v + 1];
    for (int i = s; i < e; i++) {
        int u = g_esrc[i];
        float p = g_ep[i];
        float2 xv = *(const float2*)(yin + (size_t)u * 64 + c);
        a0x += xv.x; a0y += xv.y;
        a1x += p * xv.x; a1y += p * xv.y;
    }
    float id = g_invd[v];
    float2 yv = *(const float2*)(yin + (size_t)v * 64 + c);
    float* row = g_Z + (size_t)v * 192;
    *(float2*)(row + c)        = make_float2(a0x * id, a0y * id);
    *(float2*)(row + 64 + c)   = make_float2(a1x * id, a1y * id);
    *(float2*)(row + 128 + c)  = yv;
}

__global__ void k_edge1(const float* __restrict__ b1) {
    int warp = (blockIdx.x * blockDim.x + threadIdx.x) >> 5;
    if (warp >= NN) return;
    int v = warp, lane = threadIdx.x & 31, c = lane * 2;
    float a0 = 0.f, a1 = 0.f;
    int s = g_rp[v], e = g_rp[v + 1];
    for (int i = s; i < e; i++) {
        int u = g_esrc[i];
        float p = g_ep[i];
        const float* zr = g_Z + (size_t)u * 192;
        float2 y0 = *(const float2*)(zr + c);
        float2 y1 = *(const float2*)(zr + 64 + c);
        a0 += y0.x + p * y1.x;
        a1 += y0.y + p * y1.y;
    }
    float id = g_invd[v];
    const float* zv = g_Z + (size_t)v * 192 + 128;
    float o0 = tanhf(a0 * id + zv[c]     + b1[c]);
    float o1 = tanhf(a1 * id + zv[c + 1] + b1[c + 1]);
    *(float2*)(g_h + (size_t)v * 64 + c) = make_float2(o0, o1);
}

__global__ void k_comb() {
    int i = blockIdx.x * blockDim.x + threadIdx.x;
    if (i < NN * NH) g_hf[i] = g_h[i] + 0.5f * g_ka[i];
}

__global__ void k_edge2(const float* __restrict__ b2, float* __restrict__ out) {
    int warp = (blockIdx.x * blockDim.x + threadIdx.x) >> 5;
    if (warp >= NN) return;
    int v = warp, lane = threadIdx.x & 31, c = lane & 15;
    float a = 0.f;
    int s = g_rp[v], e = g_rp[v + 1];
    for (int i = s; i < e; i++) {
        int u = g_esrc[i];
        float p = g_ep[i];
        const float* gr = g_G2 + (size_t)u * 48;
        a += gr[c] + p * gr[16 + c];
    }
    float id = g_invd[v];
    float val = tanhf(a * id + g_G2[(size_t)v * 48 + 32 + c] + b2[c]);
    float m = val;
    #pragma unroll
    for (int off = 8; off; off >>= 1)
        m = fmaxf(m, __shfl_xor_sync(0xffffffffu, m, off, 16));
    float ex = expf(val - m);
    float ssum = ex;
    #pragma unroll
    for (int off = 8; off; off >>= 1)
        ssum += __shfl_xor_sync(0xffffffffu, ssum, off, 16);
    if (lane < 16) out[(size_t)v * 16 + c] = val - m - logf(ssum);
}

// ---------------- host ----------------
extern "C" void kernel_launch(void* const* d_in, const int* in_sizes, int n_in,
                              void* d_out, int out_size) {
    const float* x     = (const float*)d_in[0];
    const float* eattr = (const float*)d_in[1];
    const int*   src   = (const int*)  d_in[2];
    const int*   dst   = (const int*)  d_in[3];
    const float* W1 = (const float*)d_in[4];
    const float* R1 = (const float*)d_in[5];
    const float* b1 = (const float*)d_in[6];
    const float* Wa = (const float*)d_in[7];
    const float* Ra = (const float*)d_in[8];
    const float* ba = (const float*)d_in[9];
    const float* Wb = (const float*)d_in[10];
    const float* Rb = (const float*)d_in[11];
    const float* bb = (const float*)d_in[12];
    const float* W2 = (const float*)d_in[13];
    const float* R2 = (const float*)d_in[14];
    const float* b2 = (const float*)d_in[15];
    float* out = (float*)d_out;

    void *pZ, *ph, *py, *pt, *pk, *pka, *phf, *pG2, *pB1, *pBA, *pBB, *pB2;
    void *pB1p, *pBAp, *pBBp, *pB2p;
    cudaGetSymbolAddress(&pZ,  g_Z);
    cudaGetSymbolAddress(&ph,  g_h);
    cudaGetSymbolAddress(&py,  g_y);
    cudaGetSymbolAddress(&pt,  g_t);
    cudaGetSymbolAddress(&pk,  g_k);
    cudaGetSymbolAddress(&pka, g_ka);
    cudaGetSymbolAddress(&phf, g_hf);
    cudaGetSymbolAddress(&pG2, g_G2);
    cudaGetSymbolAddress(&pB1, g_B1);
    cudaGetSymbolAddress(&pBA, g_BA);
    cudaGetSymbolAddress(&pBB, g_BB);
    cudaGetSymbolAddress(&pB2, g_B2);
    cudaGetSymbolAddress(&pB1p, g_B1p);
    cudaGetSymbolAddress(&pBAp, g_BAp);
    cudaGetSymbolAddress(&pBBp, g_BBp);
    cudaGetSymbolAddress(&pB2p, g_B2p);

    const int EDGE_GRID = (NN * 32 + 255) / 256;
    dim3 gemm1((NN + 127) / 128, 3);               // N=192
    dim3 gemmI((NN + 127) / 128, 1);               // N=64 (48 padded for conv2)

    // CSR build
    k_zero<<<(NN + 255) / 256, 256>>>();
    k_hist<<<(NE + 255) / 256, 256>>>(dst);
    k_scan<<<1, 1024>>>();
    k_scatter<<<(NE + 255) / 256, 256>>>(src, dst, eattr);

    // weight prep + tf32 split/permute
    k_prep_tf<<<(NF * 192 + 255) / 256, 256>>>(W1, R1, (float*)pB1, NF, NH);
    k_prep_af<<<(192 * NH + 255) / 256, 256>>>(Wa, Ra, (float*)pBA, NH);
    k_prep_af<<<(192 * NH + 255) / 256, 256>>>(Wb, Rb, (float*)pBB, NH);
    k_prep_tf<<<(NH * 48 + 255) / 256, 256>>>(W2, R2, (float*)pB2, NH, NC);
    k_permB<<<(NF * 192 + 255) / 256, 256>>>((const float*)pB1, (float*)pB1p, NF, 192, 192);
    k_permB<<<(192 * NH + 255) / 256, 256>>>((const float*)pBA, (float*)pBAp, 192, 64, 64);
    k_permB<<<(192 * NH + 255) / 256, 256>>>((const float*)pBB, (float*)pBBp, 192, 64, 64);
    k_permB<<<(NH * 64 + 255) / 256, 256>>>((const float*)pB2, (float*)pB2p, NH, 48, 64);

    // conv1: transform-first GEMM then edge pass (tanh)
    k_gemm_tc<<<gemm1, 256>>>(x, (const float*)pB1p, (float*)pZ, nullptr,
                              NN, NF, 192, 192, 192, 0, nullptr, nullptr, nullptr, 0.f, 0.f, 0);
    k_edge1<<<EDGE_GRID, 256>>>(b1);

    // RK4: k1
    k_agg<<<EDGE_GRID, 256>>>((const float*)ph);
    k_gemm_tc<<<gemmI, 256>>>((const float*)pZ, (const float*)pBAp, (float*)pt, ba,
                              NN, 192, 64, 64, 64, 0, nullptr, nullptr, nullptr, 0.f, 0.f, 0);
    k_agg<<<EDGE_GRID, 256>>>((const float*)pt);
    k_gemm_tc<<<gemmI, 256>>>((const float*)pZ, (const float*)pBBp, (float*)pk, bb,
                              NN, 192, 64, 64, 64, 1, (const float*)ph, (float*)py, (float*)pka,
                              1.5f, 1.0f, 1);
    // k2
    k_agg<<<EDGE_GRID, 256>>>((const float*)py);
    k_gemm_tc<<<gemmI, 256>>>((const float*)pZ, (const float*)pBAp, (float*)pt, ba,
                              NN, 192, 64, 64, 64, 0, nullptr, nullptr, nullptr, 0.f, 0.f, 0);
    k_agg<<<EDGE_GRID, 256>>>((const float*)pt);
    k_gemm_tc<<<gemmI, 256>>>((const float*)pZ, (const float*)pBBp, (float*)pk, bb,
                              NN, 192, 64, 64, 64, 1, (const float*)ph, (float*)py, (float*)pka,
                              1.5f, 2.0f, 0);
    // k3
    k_agg<<<EDGE_GRID, 256>>>((const float*)py);
    k_gemm_tc<<<gemmI, 256>>>((const float*)pZ, (const float*)pBAp, (float*)pt, ba,
                              NN, 192, 64, 64, 64, 0, nullptr, nullptr, nullptr, 0.f, 0.f, 0);
    k_agg<<<EDGE_GRID, 256>>>((const float*)pt);
    k_gemm_tc<<<gemmI, 256>>>((const float*)pZ, (const float*)pBBp, (float*)pk, bb,
                              NN, 192, 64, 64, 64, 1, (const float*)ph, (float*)py, (float*)pka,
                              3.0f, 2.0f, 0);
    // k4
    k_agg<<<EDGE_GRID, 256>>>((const float*)py);
    k_gemm_tc<<<gemmI, 256>>>((const float*)pZ, (const float*)pBAp, (float*)pt, ba,
                              NN, 192, 64, 64, 64, 0, nullptr, nullptr, nullptr, 0.f, 0.f, 0);
    k_agg<<<EDGE_GRID, 256>>>((const float*)pt);
    k_gemm_tc<<<gemmI, 256>>>((const float*)pZ, (const float*)pBBp, (float*)pk, bb,
                              NN, 192, 64, 64, 64, 1, (const float*)ph, nullptr, (float*)pka,
                              0.f, 1.0f, 0);

    // hf = h + 0.5*kacc ; conv2 (N padded to 64, write 48) ; softmax
    k_comb<<<(NN * NH + 255) / 256, 256>>>();
    k_gemm_tc<<<gemmI, 256>>>((const float*)phf, (const float*)pB2p, (float*)pG2, nullptr,
                              NN, 64, 64, 48, 48, 0, nullptr, nullptr, nullptr, 0.f, 0.f, 0);
    k_edge2<<<EDGE_GRID, 256>>>(b2, out);
}

// round 6
// speedup vs baseline: 1.3203x; 1.3203x over previous
#include <cuda_runtime.h>
#include <math.h>
#include <stdint.h>

#define NN 50000
#define NE 800000
#define NF 256
#define NH 64
#define NC 16

// ---------------- static scratch (no allocations allowed) ----------------
__device__ __align__(256) float g_Z [NN * 192];   // GEMM staging
__device__ __align__(256) float g_h [NN * NH];
__device__ __align__(256) float g_y [NN * NH];
__device__ __align__(256) float g_t [NN * NH];
__device__ __align__(256) float g_k [NN * NH];
__device__ __align__(256) float g_ka[NN * NH];
__device__ __align__(256) float g_hf[NN * NH];
__device__ __align__(256) float g_G2[NN * 48];
__device__ __align__(256) float g_B1[NF * 192];   // [W1_0 | W1_1-W1_0 | R1]
__device__ __align__(256) float g_BA[192 * NH];   // [Wa_0; Wa_1-Wa_0; Ra]
__device__ __align__(256) float g_BB[192 * NH];
__device__ __align__(256) float g_B2[NH * 48];
__device__ int   g_rp[NN + 1];
__device__ int   g_wp[NN];
__device__ int   g_cnt[NN];
__device__ float g_invd[NN];
__device__ __align__(256) int2 g_e[NE];           // (src, p-bits) interleaved

// ---------------- CSR build ----------------
__global__ void k_zero() {
    int i = blockIdx.x * blockDim.x + threadIdx.x;
    if (i < NN) g_cnt[i] = 0;
}

__global__ void k_hist(const int* __restrict__ dst) {
    int e = blockIdx.x * blockDim.x + threadIdx.x;
    if (e < NE) atomicAdd(&g_cnt[dst[e]], 1);
}

__global__ void k_scan() {
    __shared__ int wsum[32];
    __shared__ int carry_s;
    int tid = threadIdx.x, lane = tid & 31, wid = tid >> 5;
    if (tid == 0) carry_s = 0;
    __syncthreads();
    for (int base = 0; base < NN; base += 1024) {
        int i = base + tid;
        int v = (i < NN) ? g_cnt[i] : 0;
        int x = v;
        #pragma unroll
        for (int off = 1; off < 32; off <<= 1) {
            int t = __shfl_up_sync(0xffffffffu, x, off);
            if (lane >= off) x += t;
        }
        if (lane == 31) wsum[wid] = x;
        __syncthreads();
        if (wid == 0) {
            int s = wsum[lane];
            #pragma unroll
            for (int off = 1; off < 32; off <<= 1) {
                int t = __shfl_up_sync(0xffffffffu, s, off);
                if (lane >= off) s += t;
            }
            wsum[lane] = s;
        }
        __syncthreads();
        int excl = carry_s + (wid > 0 ? wsum[wid - 1] : 0) + x - v;
        if (i < NN) {
            g_rp[i]  = excl;
            g_wp[i]  = excl;
            g_invd[i] = 1.0f / (float)(v > 0 ? v : 1);
        }
        __syncthreads();
        if (tid == 0) carry_s += wsum[31];
        __syncthreads();
    }
    if (threadIdx.x == 0) g_rp[NN] = carry_s;
}

__global__ void k_scatter(const int* __restrict__ src, const int* __restrict__ dst,
                          const float* __restrict__ p) {
    int e = blockIdx.x * blockDim.x + threadIdx.x;
    if (e < NE) {
        int d   = dst[e];
        int pos = atomicAdd(&g_wp[d], 1);
        g_e[pos] = make_int2(src[e], __float_as_int(p[e]));
    }
}

// ---------------- weight prep ----------------
__global__ void k_prep_tf(const float* __restrict__ W, const float* __restrict__ R,
                          float* __restrict__ B, int Cin, int Cout) {
    int i = blockIdx.x * blockDim.x + threadIdx.x;
    int tot = Cin * 3 * Cout;
    if (i >= tot) return;
    int r = i / (3 * Cout), c = i % (3 * Cout);
    float v;
    if (c < Cout)            v = W[r * Cout + c];
    else if (c < 2 * Cout)   v = W[Cin * Cout + r * Cout + (c - Cout)] - W[r * Cout + (c - Cout)];
    else                     v = R[r * Cout + (c - 2 * Cout)];
    B[i] = v;
}

__global__ void k_prep_af(const float* __restrict__ W, const float* __restrict__ R,
                          float* __restrict__ B, int C) {
    int i = blockIdx.x * blockDim.x + threadIdx.x;
    int tot = 3 * C * C;
    if (i >= tot) return;
    int r = i / C, c = i % C;
    float v;
    if (r < C)          v = W[r * C + c];
    else if (r < 2 * C) v = W[C * C + (r - C) * C + c] - W[(r - C) * C + c];
    else                v = R[(r - 2 * C) * C + c];
    B[i] = v;
}

// ---------------- GEMM: C[M,N] = A[M,K] @ B[K,N] (+bias) (+RK4 epilogue) ----------------
// 128x64 block tile, 128 threads, 8x8 per thread, BK=16. K % 16 == 0.
// mode 0: plain. mode 1: ynext = h + ccoef*v ; kacc (+)= wcoef*v.
// mode 2: ynext = h + 0.5*(kacc + v)   (final RK4 combine; kacc read-only)
__global__ void __launch_bounds__(128) k_gemm(
    const float* __restrict__ A, const float* __restrict__ B,
    float* __restrict__ C, const float* __restrict__ bias,
    int M, int K, int N, int ldc,
    int mode, const float* __restrict__ hin, float* __restrict__ ynext,
    float* __restrict__ kacc, float ccoef, float wcoef, int kinit)
{
    __shared__ float As[16][128];
    __shared__ float Bs[16][64];
    int tid = threadIdx.x;
    int bm = blockIdx.x * 128;
    int bn = blockIdx.y * 64;
    int trow = (tid >> 3) * 8;   // 0..120
    int tcol = (tid & 7) * 8;    // 0..56

    float acc[8][8];
    #pragma unroll
    for (int i = 0; i < 8; i++)
        #pragma unroll
        for (int j = 0; j < 8; j++) acc[i][j] = 0.0f;

    for (int k0 = 0; k0 < K; k0 += 16) {
        // A tile: 128x16 = 512 float4, 4 per thread
        #pragma unroll
        for (int q = 0; q < 4; q++) {
            int l = q * 128 + tid;
            int m = l >> 2;
            int kk = (l & 3) * 4;
            int gr = bm + m;
            float4 av = make_float4(0.f, 0.f, 0.f, 0.f);
            if (gr < M) av = *(const float4*)(A + (size_t)gr * K + k0 + kk);
            As[kk + 0][m] = av.x; As[kk + 1][m] = av.y;
            As[kk + 2][m] = av.z; As[kk + 3][m] = av.w;
        }
        // B tile: 16x64 = 256 float4, 2 per thread (guard cols for N<64)
        #pragma unroll
        for (int q = 0; q < 2; q++) {
            int l = q * 128 + tid;
            int br = l >> 4;
            int bc = (l & 15) * 4;
            int gc = bn + bc;
            float4 bv;
            if (gc + 3 < N) {
                bv = *(const float4*)(B + (size_t)(k0 + br) * N + gc);
            } else {
                bv.x = (gc + 0 < N) ? B[(size_t)(k0 + br) * N + gc + 0] : 0.f;
                bv.y = (gc + 1 < N) ? B[(size_t)(k0 + br) * N + gc + 1] : 0.f;
                bv.z = (gc + 2 < N) ? B[(size_t)(k0 + br) * N + gc + 2] : 0.f;
                bv.w = (gc + 3 < N) ? B[(size_t)(k0 + br) * N + gc + 3] : 0.f;
            }
            *(float4*)&Bs[br][bc] = bv;
        }
        __syncthreads();
        #pragma unroll
        for (int kk = 0; kk < 16; kk++) {
            float4 a0 = *(const float4*)&As[kk][trow];
            float4 a1 = *(const float4*)&As[kk][trow + 4];
            float4 b0 = *(const float4*)&Bs[kk][tcol];
            float4 b1 = *(const float4*)&Bs[kk][tcol + 4];
            float a[8] = {a0.x, a0.y, a0.z, a0.w, a1.x, a1.y, a1.z, a1.w};
            float b[8] = {b0.x, b0.y, b0.z, b0.w, b1.x, b1.y, b1.z, b1.w};
            #pragma unroll
            for (int i = 0; i < 8; i++)
                #pragma unroll
                for (int j = 0; j < 8; j++)
                    acc[i][j] += a[i] * b[j];
        }
        __syncthreads();
    }

    #pragma unroll
    for (int i = 0; i < 8; i++) {
        int r = bm + trow + i;
        if (r >= M) continue;
        #pragma unroll
        for (int j = 0; j < 8; j++) {
            int gc = bn + tcol + j;
            if (gc >= N) continue;
            float v = acc[i][j];
            if (bias) v += bias[gc];
            C[(size_t)r * ldc + gc] = v;
            if (mode == 1) {
                size_t ei = (size_t)r * 64 + gc;   // N==64 path
                if (ynext) ynext[ei] = hin[ei] + ccoef * v;
                kacc[ei] = kinit ? wcoef * v : kacc[ei] + wcoef * v;
            } else if (mode == 2) {
                size_t ei = (size_t)r * 64 + gc;
                ynext[ei] = hin[ei] + 0.5f * (kacc[ei] + v);
            }
        }
    }
}

// ---------------- edge kernels (CSR, warp per node) ----------------
// aggregate-first: Z[v] = [invd*sum x_src | invd*sum p*x_src | x_v]
__global__ void k_agg(const float* __restrict__ yin) {
    int warp = (blockIdx.x * blockDim.x + threadIdx.x) >> 5;
    if (warp >= NN) return;
    int v = warp, lane = threadIdx.x & 31, c = lane * 2;
    float a0x = 0.f, a0y = 0.f, a1x = 0.f, a1y = 0.f;
    int s = g_rp[v], e = g_rp[v + 1];
    for (int i = s; i < e; i++) {
        int2 ed = g_e[i];
        float p = __int_as_float(ed.y);
        float2 xv = *(const float2*)(yin + (size_t)ed.x * 64 + c);
        a0x += xv.x; a0y += xv.y;
        a1x += p * xv.x; a1y += p * xv.y;
    }
    float id = g_invd[v];
    float2 yv = *(const float2*)(yin + (size_t)v * 64 + c);
    float* row = g_Z + (size_t)v * 192;
    *(float2*)(row + c)        = make_float2(a0x * id, a0y * id);
    *(float2*)(row + 64 + c)   = make_float2(a1x * id, a1y * id);
    *(float2*)(row + 128 + c)  = yv;
}

// conv1 edge pass (transform-first, Cout=64) + bias + tanh -> g_h
__global__ void k_edge1(const float* __restrict__ b1) {
    int warp = (blockIdx.x * blockDim.x + threadIdx.x) >> 5;
    if (warp >= NN) return;
    int v = warp, lane = threadIdx.x & 31, c = lane * 2;
    float a0 = 0.f, a1 = 0.f;
    int s = g_rp[v], e = g_rp[v + 1];
    for (int i = s; i < e; i++) {
        int2 ed = g_e[i];
        float p = __int_as_float(ed.y);
        const float* zr = g_Z + (size_t)ed.x * 192;
        float2 y0 = *(const float2*)(zr + c);
        float2 y1 = *(const float2*)(zr + 64 + c);
        a0 += y0.x + p * y1.x;
        a1 += y0.y + p * y1.y;
    }
    float id = g_invd[v];
    const float* zv = g_Z + (size_t)v * 192 + 128;
    float o0 = tanhf(a0 * id + zv[c]     + b1[c]);
    float o1 = tanhf(a1 * id + zv[c + 1] + b1[c + 1]);
    *(float2*)(g_h + (size_t)v * 64 + c) = make_float2(o0, o1);
}

// conv2 edge pass (transform-first, Cout=16) + bias + tanh + log_softmax
__global__ void k_edge2(const float* __restrict__ b2, float* __restrict__ out) {
    int warp = (blockIdx.x * blockDim.x + threadIdx.x) >> 5;
    if (warp >= NN) return;
    int v = warp, lane = threadIdx.x & 31, c = lane & 15;
    float a = 0.f;
    int s = g_rp[v], e = g_rp[v + 1];
    for (int i = s; i < e; i++) {
        int2 ed = g_e[i];
        float p = __int_as_float(ed.y);
        const float* gr = g_G2 + (size_t)ed.x * 48;
        a += gr[c] + p * gr[16 + c];
    }
    float id = g_invd[v];
    float val = tanhf(a * id + g_G2[(size_t)v * 48 + 32 + c] + b2[c]);
    float m = val;
    #pragma unroll
    for (int off = 8; off; off >>= 1)
        m = fmaxf(m, __shfl_xor_sync(0xffffffffu, m, off, 16));
    float ex = expf(val - m);
    float ssum = ex;
    #pragma unroll
    for (int off = 8; off; off >>= 1)
        ssum += __shfl_xor_sync(0xffffffffu, ssum, off, 16);
    if (lane < 16) out[(size_t)v * 16 + c] = val - m - logf(ssum);
}

// ---------------- host ----------------
extern "C" void kernel_launch(void* const* d_in, const int* in_sizes, int n_in,
                              void* d_out, int out_size) {
    const float* x     = (const float*)d_in[0];
    const float* eattr = (const float*)d_in[1];
    const int*   src   = (const int*)  d_in[2];
    const int*   dst   = (const int*)  d_in[3];
    const float* W1 = (const float*)d_in[4];
    const float* R1 = (const float*)d_in[5];
    const float* b1 = (const float*)d_in[6];
    const float* Wa = (const float*)d_in[7];
    const float* Ra = (const float*)d_in[8];
    const float* ba = (const float*)d_in[9];
    const float* Wb = (const float*)d_in[10];
    const float* Rb = (const float*)d_in[11];
    const float* bb = (const float*)d_in[12];
    const float* W2 = (const float*)d_in[13];
    const float* R2 = (const float*)d_in[14];
    const float* b2 = (const float*)d_in[15];
    float* out = (float*)d_out;

    void *pZ, *ph, *py, *pt, *pk, *pka, *phf, *pG2, *pB1, *pBA, *pBB, *pB2;
    cudaGetSymbolAddress(&pZ,  g_Z);
    cudaGetSymbolAddress(&ph,  g_h);
    cudaGetSymbolAddress(&py,  g_y);
    cudaGetSymbolAddress(&pt,  g_t);
    cudaGetSymbolAddress(&pk,  g_k);
    cudaGetSymbolAddress(&pka, g_ka);
    cudaGetSymbolAddress(&phf, g_hf);
    cudaGetSymbolAddress(&pG2, g_G2);
    cudaGetSymbolAddress(&pB1, g_B1);
    cudaGetSymbolAddress(&pBA, g_BA);
    cudaGetSymbolAddress(&pBB, g_BB);
    cudaGetSymbolAddress(&pB2, g_B2);

    const int EDGE_GRID = (NN * 32 + 255) / 256;   // warp per node
    dim3 gemm1((NN + 127) / 128, 3);               // N=192
    dim3 gemmI((NN + 127) / 128, 1);               // N=64 or 48

    // Launch order chosen so the conv1 GEMM lands at launch index 3
    // (the slot ncu's -s/-c bounds captured in both previous profiled runs).
    k_prep_tf<<<(NF * 192 + 255) / 256, 256>>>(W1, R1, (float*)pB1, NF, NH);   // 0
    k_zero<<<(NN + 255) / 256, 256>>>();                                       // 1
    k_hist<<<(NE + 255) / 256, 256>>>(dst);                                    // 2
    k_gemm<<<gemm1, 128>>>(x, (const float*)pB1, (float*)pZ, nullptr,          // 3  <- profiled
                           NN, NF, 192, 192, 0, nullptr, nullptr, nullptr, 0.f, 0.f, 0);
    k_scan<<<1, 1024>>>();                                                     // 4
    k_scatter<<<(NE + 255) / 256, 256>>>(src, dst, eattr);                     // 5

    // remaining weight prep
    k_prep_af<<<(192 * NH + 255) / 256, 256>>>(Wa, Ra, (float*)pBA, NH);
    k_prep_af<<<(192 * NH + 255) / 256, 256>>>(Wb, Rb, (float*)pBB, NH);
    k_prep_tf<<<(NH * 48 + 255) / 256, 256>>>(W2, R2, (float*)pB2, NH, NC);

    // conv1 edge pass (tanh)
    k_edge1<<<EDGE_GRID, 256>>>(b1);

    // RK4: k1
    k_agg<<<EDGE_GRID, 256>>>((const float*)ph);
    k_gemm<<<gemmI, 128>>>((const float*)pZ, (const float*)pBA, (float*)pt, ba,
                           NN, 192, 64, 64, 0, nullptr, nullptr, nullptr, 0.f, 0.f, 0);
    k_agg<<<EDGE_GRID, 256>>>((const float*)pt);
    k_gemm<<<gemmI, 128>>>((const float*)pZ, (const float*)pBB, (float*)pk, bb,
                           NN, 192, 64, 64, 1, (const float*)ph, (float*)py, (float*)pka,
                           1.5f, 1.0f, 1);
    // k2
    k_agg<<<EDGE_GRID, 256>>>((const float*)py);
    k_gemm<<<gemmI, 128>>>((const float*)pZ, (const float*)pBA, (float*)pt, ba,
                           NN, 192, 64, 64, 0, nullptr, nullptr, nullptr, 0.f, 0.f, 0);
    k_agg<<<EDGE_GRID, 256>>>((const float*)pt);
    k_gemm<<<gemmI, 128>>>((const float*)pZ, (const float*)pBB, (float*)pk, bb,
                           NN, 192, 64, 64, 1, (const float*)ph, (float*)py, (float*)pka,
                           1.5f, 2.0f, 0);
    // k3
    k_agg<<<EDGE_GRID, 256>>>((const float*)py);
    k_gemm<<<gemmI, 128>>>((const float*)pZ, (const float*)pBA, (float*)pt, ba,
                           NN, 192, 64, 64, 0, nullptr, nullptr, nullptr, 0.f, 0.f, 0);
    k_agg<<<EDGE_GRID, 256>>>((const float*)pt);
    k_gemm<<<gemmI, 128>>>((const float*)pZ, (const float*)pBB, (float*)pk, bb,
                           NN, 192, 64, 64, 1, (const float*)ph, (float*)py, (float*)pka,
                           3.0f, 2.0f, 0);
    // k4 + fused final combine: hf = h + 0.5*(ka + k4)
    k_agg<<<EDGE_GRID, 256>>>((const float*)py);
    k_gemm<<<gemmI, 128>>>((const float*)pZ, (const float*)pBA, (float*)pt, ba,
                           NN, 192, 64, 64, 0, nullptr, nullptr, nullptr, 0.f, 0.f, 0);
    k_agg<<<EDGE_GRID, 256>>>((const float*)pt);
    k_gemm<<<gemmI, 128>>>((const float*)pZ, (const float*)pBB, (float*)pk, bb,
                           NN, 192, 64, 64, 2, (const float*)ph, (float*)phf, (float*)pka,
                           0.f, 1.0f, 0);

    // conv2 ; softmax
    k_gemm<<<gemmI, 128>>>((const float*)phf, (const float*)pB2, (float*)pG2, nullptr,
                           NN, 64, 48, 48, 0, nullptr, nullptr, nullptr, 0.f, 0.f, 0);
    k_edge2<<<EDGE_GRID, 256>>>(b2, out);
}